// round 14
// baseline (speedup 1.0000x reference)
#include <cuda_runtime.h>
#include <cstdint>

#define D 128
#define NVOX (D * D * D)
#define FULL 0xFFFFFFFFu

// fused: 4x8x8 tiles, gather straight from AoS x (L1-resident per tile)
__global__ void __launch_bounds__(256)
ca_fused_kernel(const float* __restrict__ x,
                const float* __restrict__ out,
                float* __restrict__ y)
{
    __shared__ __align__(16) float ly[256 * 5];   // [32 rows][40 floats]

    const int tid  = threadIdx.x;
    const int lane = tid & 31;

    // tile decode: 32 x 16 x 16 tiles of 4x8x8
    const int bid = blockIdx.x;
    const int tk = bid & 15;
    const int tj = (bid >> 4) & 15;
    const int ti = bid >> 8;
    const int i0 = ti * 4, j0 = tj * 8, k0 = tk * 8;

    const int li = tid >> 6;
    const int lj = (tid >> 3) & 7;
    const int lk = tid & 7;
    const int gi = i0 + li, gj = j0 + lj, gk = k0 + lk;
    const int v  = (gi * D + gj) * D + gk;

    // own x values: scalar loads, lines stay in L1 for the gather
    const float* xv = x + (size_t)v * 5;
    float s0f = xv[0];
    float y_e0 = xv[1];
    float y_e1 = xv[2];
    float y_e2 = xv[3];
    int state0 = (int)s0f;

    const float4* o4 = reinterpret_cast<const float4*>(out + (size_t)v * 8);
    float4 oa = __ldcs(o4 + 0);
    float4 ob = __ldcs(o4 + 1);

    int   state1 = 0;
    float bst    = oa.x;
    if (oa.y > bst) { bst = oa.y; state1 = 1; }
    if (oa.z > bst) { bst = oa.z; state1 = 2; }
    if (oa.w > bst) { bst = oa.w; state1 = 3; }
    if (state0 == 0) state1 = 0;

    float field1 = ob.w;
    if (state1 <= 1) {
        field1 = -1.0f;
        y_e0 = -1.0f; y_e1 = -1.0f; y_e2 = -1.0f;
    } else if (state1 == 2) {
        field1 = fminf(fmaxf(field1, 0.0f), 0.92f);
    } else {
        field1 = 1.0f;
    }

    // warp-cooperative 26-neighbor argmin, MLP-2, L1-resident x gather
    bool flag = (state0 <= 1) && (state1 > 1);
    unsigned mask = __ballot_sync(FULL, flag);

    int c26 = lane + (lane >= 13 ? 1 : 0);
    int di = c26 / 9 - 1;
    int dj = (c26 / 3) % 3 - 1;
    int dk = c26 % 3 - 1;
    int noff = ((di * D + dj) * D + dk) * 5;   // element offset in x
    const bool gl = (lane < 26);

    while (mask) {
        int srcA = __ffs(mask) - 1;
        mask &= mask - 1;
        int srcB = -1;
        if (mask) { srcB = __ffs(mask) - 1; mask &= mask - 1; }

        int vvA = __shfl_sync(FULL, v, srcA);
        int vvB = __shfl_sync(FULL, v, srcB < 0 ? srcA : srcB);

        // per-lane bounds for both voxels
        bool okA = false, okB = false;
        if (gl) {
            int ia = (vvA >> 14) + di, ja = ((vvA >> 7) & 127) + dj,
                ka = (vvA & 127) + dk;
            okA = ((unsigned)ia < (unsigned)D) & ((unsigned)ja < (unsigned)D) &
                  ((unsigned)ka < (unsigned)D);
            int ib = (vvB >> 14) + di, jb = ((vvB >> 7) & 127) + dj,
                kb = (vvB & 127) + dk;
            okB = (srcB >= 0) &
                  ((unsigned)ib < (unsigned)D) & ((unsigned)jb < (unsigned)D) &
                  ((unsigned)kb < (unsigned)D);
        }

        // issue all gather loads before any dependent math (MLP)
        const float* pA = x + (size_t)vvA * 5 + noff;
        const float* pB = x + (size_t)vvB * 5 + noff;
        float a0 = 0.f, a1 = 0.f, a2 = 0.f;
        float b0 = 0.f, b1 = 0.f, b2 = 0.f;
        if (okA) { a0 = pA[1]; a1 = pA[2]; a2 = pA[3]; }
        if (okB) { b0 = pB[1]; b1 = pB[2]; b2 = pB[3]; }

        float rxA = __shfl_sync(FULL, ob.x, srcA);
        float ryA = __shfl_sync(FULL, ob.y, srcA);
        float rzA = __shfl_sync(FULL, ob.z, srcA);
        {
            float d0 = a0 - rxA, d1 = a1 - ryA, d2 = a2 - rzA;
            float dist = d0 * d0 + d1 * d1 + d2 * d2;
            unsigned key = gl ? ((__float_as_uint(dist) & ~31u) | lane)
                              : 0xFFFFFFFFu;
            unsigned kmin = __reduce_min_sync(FULL, key);
            int s = (int)(kmin & 31u);
            float w0 = __shfl_sync(FULL, a0, s);
            float w1 = __shfl_sync(FULL, a1, s);
            float w2 = __shfl_sync(FULL, a2, s);
            if (lane == srcA) { y_e0 = w0; y_e1 = w1; y_e2 = w2; }
        }
        if (srcB >= 0) {
            float rxB = __shfl_sync(FULL, ob.x, srcB);
            float ryB = __shfl_sync(FULL, ob.y, srcB);
            float rzB = __shfl_sync(FULL, ob.z, srcB);
            float d0 = b0 - rxB, d1 = b1 - ryB, d2 = b2 - rzB;
            float dist = d0 * d0 + d1 * d1 + d2 * d2;
            unsigned key = gl ? ((__float_as_uint(dist) & ~31u) | lane)
                              : 0xFFFFFFFFu;
            unsigned kmin = __reduce_min_sync(FULL, key);
            int s = (int)(kmin & 31u);
            float w0 = __shfl_sync(FULL, b0, s);
            float w1 = __shfl_sync(FULL, b1, s);
            float w2 = __shfl_sync(FULL, b2, s);
            if (lane == srcB) { y_e0 = w0; y_e1 = w1; y_e2 = w2; }
        }
    }

    // stage outputs: row = li*8+lj (0..31), 40 floats per row
    const int row = tid >> 3;
    ly[row * 40 + lk * 5 + 0] = (float)state1;
    ly[row * 40 + lk * 5 + 1] = y_e0;
    ly[row * 40 + lk * 5 + 2] = y_e1;
    ly[row * 40 + lk * 5 + 3] = y_e2;
    ly[row * 40 + lk * 5 + 4] = field1;
    __syncthreads();

    // 32 rows x 10 float4; row base 16B-aligned (k0 % 8 == 0)
    for (int f = tid; f < 320; f += 256) {
        int r    = f / 10;
        int part = f - r * 10;
        int ri = i0 + (r >> 3);
        int rj = j0 + (r & 7);
        long gbase = (((long)ri * D + rj) * D + k0) * 5 + part * 4;
        __stcs(reinterpret_cast<float4*>(y + gbase),
               *reinterpret_cast<const float4*>(&ly[r * 40 + part * 4]));
    }
}

extern "C" void kernel_launch(void* const* d_in, const int* in_sizes, int n_in,
                              void* d_out, int out_size)
{
    const float* x   = (const float*)d_in[0];
    const float* out = (const float*)d_in[1];
    if (n_in >= 2 && in_sizes[0] == 8 * NVOX && in_sizes[1] == 5 * NVOX) {
        const float* t = x; x = out; out = t;
    }
    float* y = (float*)d_out;

    ca_fused_kernel<<<8192, 256>>>(x, out, y);
}